// round 3
// baseline (speedup 1.0000x reference)
#include <cuda_runtime.h>

// HashEncoder: D=3, L=16, C=2, BASE=16, PLS=2, T=2^19, B=2^21
// Levels 0..2 dense (res^3 <= T), levels 3..15 hashed into T=524288 entries.
// Output: [B, 32] float32, level-major channel pairs.
//
// Corner-pair trick: with ix0 clamped to res-2 (fx allowed to reach 1.0 —
// identical math to the reference's corner clamp), the second x-corner index
// is i0^1 whenever ix0 is even, in BOTH dense and hashed addressing. A single
// aligned float4 load at (i0 & ~1) then covers both x-corners for even-x
// lanes at the cost of the old single-corner float2 load (same 32B sector).

#define NPOINTS  2097152
#define NLEV     16
#define TSIZE    524288u
#define HMASK    524287u
#define PRIME1   2654435761u
#define PRIME2   805459861u
#define BLOCK    256
#define SPITCH   36   // floats per point row in smem (mult of 4, phase-friendly)

__device__ static constexpr int OFFS[16] = {
    0, 4096, 36864, 299008,
    823296, 1347584, 1871872, 2396160,
    2920448, 3444736, 3969024, 4493312,
    5017600, 5541888, 6066176, 6590464
};

__global__ void __launch_bounds__(BLOCK)
hash_encode_kernel(const float* __restrict__ in,
                   const float* __restrict__ emb,
                   float* __restrict__ out)
{
    __shared__ float s_out[BLOCK * SPITCH];   // 36 KB

    const int tid = threadIdx.x;
    const long long p = (long long)blockIdx.x * BLOCK + tid;

    const float x = in[p * 3 + 0];
    const float y = in[p * 3 + 1];
    const float z = in[p * 3 + 2];

#pragma unroll
    for (int l = 0; l < NLEV; l++) {
        const int res = 16 << l;                 // exact: ceil(16 * 2^l)
        const float scale = (float)(res - 1);

        const float px = x * scale;
        const float py = y * scale;
        const float pz = z * scale;

        // Clamp the base corner to res-2; frac may reach 1.0. Equivalent to
        // the reference's corner clamp (the shifted cell gives w=1 on the
        // boundary corner, w=0 on the other).
        int ix0 = min(__float2int_rd(px), res - 2);
        int iy0 = min(__float2int_rd(py), res - 2);
        int iz0 = min(__float2int_rd(pz), res - 2);

        const float fx = px - (float)ix0;
        const float fy = py - (float)iy0;
        const float fz = pz - (float)iz0;

        const float wx0 = 1.0f - fx;
        const float wyz[4] = {(1.0f - fy) * (1.0f - fz),
                              fy * (1.0f - fz),
                              (1.0f - fy) * fz,
                              fy * fz};

        const float2* __restrict__ e = (const float2*)emb + OFFS[l];

        const bool dense = ((long long)res * res * res) <= (long long)TSIZE; // compile-time
        const unsigned ux0 = (unsigned)ix0;
        const bool xeven = (ux0 & 1u) == 0u;

        unsigned yz[4];
        if (dense) {
            const unsigned r  = (unsigned)res;
            const unsigned r2 = r * r;
            yz[0] = (unsigned)iy0 * r       + (unsigned)iz0 * r2;
            yz[1] = ((unsigned)iy0 + 1u) * r + (unsigned)iz0 * r2;
            yz[2] = (unsigned)iy0 * r       + ((unsigned)iz0 + 1u) * r2;
            yz[3] = ((unsigned)iy0 + 1u) * r + ((unsigned)iz0 + 1u) * r2;
        } else {
            const unsigned hy0 = (unsigned)iy0 * PRIME1;
            const unsigned hy1 = ((unsigned)iy0 + 1u) * PRIME1;
            const unsigned hz0 = (unsigned)iz0 * PRIME2;
            const unsigned hz1 = ((unsigned)iz0 + 1u) * PRIME2;
            yz[0] = hy0 ^ hz0;
            yz[1] = hy1 ^ hz0;
            yz[2] = hy0 ^ hz1;
            yz[3] = hy1 ^ hz1;
        }

        float r0 = 0.0f, r1 = 0.0f;

#pragma unroll
        for (int c = 0; c < 4; c++) {
            unsigned i0, i1;
            if (dense) {
                i0 = ux0 + yz[c];
                i1 = i0 + 1u;
            } else {
                i0 = (ux0 ^ yz[c]) & HMASK;
                i1 = ((ux0 + 1u) ^ yz[c]) & HMASK;
            }

            // Corner 0 (and, for even-x lanes, corner 1) from one float4.
            const float4 A = __ldg((const float4*)(e + (i0 & ~1u)));
            const bool hi = (i0 & 1u) != 0u;

            float2 c0, c1;
            c0.x = hi ? A.z : A.x;
            c0.y = hi ? A.w : A.y;

            if (xeven) {
                c1.x = hi ? A.x : A.z;
                c1.y = hi ? A.y : A.w;
            } else {
                c1 = __ldg(e + i1);
            }

            const float w0 = wx0 * wyz[c];
            const float w1 = fx  * wyz[c];
            r0 = fmaf(w0, c0.x, r0);
            r1 = fmaf(w0, c0.y, r1);
            r0 = fmaf(w1, c1.x, r0);
            r1 = fmaf(w1, c1.y, r1);
        }

        *(float2*)&s_out[tid * SPITCH + 2 * l] = make_float2(r0, r1);
    }

    __syncthreads();

    // Coalesced vectorized store of the block's [256 x 32] tile.
    float4* __restrict__ out4 = (float4*)(out + (long long)blockIdx.x * BLOCK * 32);
#pragma unroll
    for (int i = tid; i < BLOCK * 8; i += BLOCK) {
        const int pp = i >> 3;        // point within block
        const int e4 = i & 7;         // float4 within the 32-float row
        out4[i] = *(const float4*)&s_out[pp * SPITCH + e4 * 4];
    }
}

extern "C" void kernel_launch(void* const* d_in, const int* in_sizes, int n_in,
                              void* d_out, int out_size)
{
    const float* in  = (const float*)d_in[0];   // [B,3] float32
    const float* emb = (const float*)d_in[1];   // [TOTAL_PARAMS,2] float32
    float* out = (float*)d_out;                 // [B,32] float32

    hash_encode_kernel<<<NPOINTS / BLOCK, BLOCK>>>(in, emb, out);
}